// round 17
// baseline (speedup 1.0000x reference)
#include <cuda_runtime.h>
#include <cuda_fp16.h>
#include <cstdint>

#define N_DIM 512

// ---------------- scratch ----------------
__device__ __half g_P[(size_t)100000 * 128];   // fp16 P (25.6MB): [0..63]=s, [64..127]=o

// ---------------- smem layout ----------------
// [0, 131072)       B static: 128 rows x 1024B fp16, granule-swizzled
// [131072, +49152)  A: 2 stages x 192 rows x 128B fp16
#define A_OFF      131072
#define A_STAGE_B  24576
#define SMEM_BYTES (131072 + 2 * A_STAGE_B)    // 180224

// swizzle: byte col c in row r -> c ^ ((r&7)*16)
#define FSW(r) ((uint32_t)(((r) & 7) << 4))

// ---------------- helpers ----------------
__device__ __forceinline__ uint32_t smem_u32(const void* p) {
    uint32_t a;
    asm("{ .reg .u64 t; cvta.to.shared.u64 t, %1; cvt.u32.u64 %0, t; }" : "=r"(a) : "l"(p));
    return a;
}
__device__ __forceinline__ void ldsm4(uint32_t r[4], uint32_t a) {
    asm volatile("ldmatrix.sync.aligned.m8n8.x4.shared.b16 {%0,%1,%2,%3}, [%4];"
                 : "=r"(r[0]), "=r"(r[1]), "=r"(r[2]), "=r"(r[3]) : "r"(a));
}
__device__ __forceinline__ void hmma16816(float d[4], const uint32_t a[4], uint32_t b0, uint32_t b1) {
    asm volatile("mma.sync.aligned.m16n8k16.row.col.f32.f16.f16.f32 "
                 "{%0,%1,%2,%3},{%4,%5,%6,%7},{%8,%9},{%0,%1,%2,%3};"
                 : "+f"(d[0]), "+f"(d[1]), "+f"(d[2]), "+f"(d[3])
                 : "r"(a[0]), "r"(a[1]), "r"(a[2]), "r"(a[3]), "r"(b0), "r"(b1));
}
__device__ __forceinline__ uint32_t pack_h2(float x, float y) {
    __half2 h = __floats2half2_rn(x, y);
    return *reinterpret_cast<uint32_t*>(&h);
}

// ---------------- kernel 1: persistent P = emb @ B^T; B built in-CTA from W; A 2-stage reg hop ----------------
__global__ __launch_bounds__(384, 1) void gemm_kernel(const float* __restrict__ emb,
                                                      const float* __restrict__ W,
                                                      int n_nodes, int ntiles, int grid) {
    extern __shared__ char smem[];
    const uint32_t sb = smem_u32(smem);
    const int tid = threadIdx.x;
    const int lane = tid & 31;
    const int wid = tid >> 5;
    const int wm = wid % 6;     // 6 M-tiles of 32 (CTA M=192)
    const int wn = wid / 6;     // 2 N-tiles of 64
    const int bid = blockIdx.x;

    const int ntiles_mine = (ntiles - bid + grid - 1) / grid;
    const int gtot = ntiles_mine * 8;

    // A granules: chunk = 192 rows x 16 fp32-granules = 3072; thread t owns {t + 384 i}
    int arowv[8], acolv[8];
    #pragma unroll
    for (int i = 0; i < 8; i++) {
        int gidx = tid + i * 384;
        arowv[i] = gidx >> 4;
        acolv[i] = gidx & 15;
    }

    float4 buf[8];              // A chunk in flight

    auto LDGA = [&](int g) {
        if (g >= gtot) return;
        const int tile = bid + (g >> 3) * grid;
        const int c = g & 7;
        const int ctaM = tile * 192;
        #pragma unroll
        for (int i = 0; i < 8; i++) {
            int ar = ctaM + arowv[i];
            if (ar >= n_nodes) ar = n_nodes - 1;
            buf[i] = *(const float4*)(emb + (size_t)ar * N_DIM + c * 64 + acolv[i] * 4);
        }
    };
    auto STSA = [&](int g) {
        if (g >= gtot) return;
        const uint32_t aOff = A_OFF + (g & 1) * A_STAGE_B;
        #pragma unroll
        for (int i = 0; i < 8; i++) {
            uint2 h = make_uint2(pack_h2(buf[i].x, buf[i].y), pack_h2(buf[i].z, buf[i].w));
            *(uint2*)(smem + aOff + arowv[i] * 128 +
                      (((uint32_t)(acolv[i] * 8)) ^ FSW(arowv[i]))) = h;
        }
    };

    // ---- prologue: A chunk 0 LDG first (DRAM latency shadowed by B build) ----
    LDGA(0);

    // build swizzled fp16 B image from W: granule i -> row n = i>>6, gk = i&63
    for (int i = tid; i < 8192; i += 384) {
        int n = i >> 6, gk = i & 63;
        const float* src = (n < 64) ? (W + (size_t)n * 1024 + gk * 8)
                                    : (W + (size_t)(n - 64) * 1024 + 512 + gk * 8);
        float4 v0 = *(const float4*)src;
        float4 v1 = *(const float4*)(src + 4);
        uint4 h;
        h.x = pack_h2(v0.x, v0.y); h.y = pack_h2(v0.z, v0.w);
        h.z = pack_h2(v1.x, v1.y); h.w = pack_h2(v1.z, v1.w);
        *(uint4*)(smem + (size_t)(n * 64 + (gk ^ (n & 7))) * 16) = h;
    }

    STSA(0);             // A chunk 0 regs -> smem (LDG latency long since covered)
    LDGA(1);             // chunk 1 into regs

    float acc[2][8][4];
    #pragma unroll
    for (int i = 0; i < 2; i++)
        #pragma unroll
        for (int j = 0; j < 8; j++)
            #pragma unroll
            for (int k = 0; k < 4; k++) acc[i][j][k] = 0.0f;

    __syncthreads();     // B image + everyone's STSA(0) visible

    // consumer lane constants
    const int a_lrow = lane & 15;
    const uint32_t a_lcol = (uint32_t)((lane >> 4) * 16);
    const int b_lrow = (lane & 7) + ((lane >> 4) & 1) * 8;   // R3-proven B lane map
    const uint32_t b_lcol = (uint32_t)(((lane >> 3) & 1) * 16);

    for (int g = 0; g < gtot; g++) {
        // entry invariant: slot g&1 holds chunk g (visible); buf holds chunk g+1
        STSA(g + 1);     // writes slot (g+1)&1 (old contents consumed before last barrier)
        LDGA(g + 2);     // refill buf (program-order WAR after STSA)

        const uint32_t aOff = A_OFF + (g & 1) * A_STAGE_B;
        const int c = g & 7;

        #pragma unroll
        for (int ks = 0; ks < 4; ks++) {
            uint32_t afr[2][4];
            #pragma unroll
            for (int mt = 0; mt < 2; mt++) {
                const int row = wm * 32 + mt * 16 + a_lrow;
                ldsm4(afr[mt], sb + aOff + row * 128 + (((uint32_t)(ks * 32) + a_lcol) ^ FSW(row)));
            }
            uint32_t bfr[4][4];
            #pragma unroll
            for (int p = 0; p < 4; p++) {
                const int rn = wn * 64 + p * 16 + b_lrow;
                ldsm4(bfr[p], sb + rn * 1024 +
                              (((uint32_t)(c * 128 + ks * 32) + b_lcol) ^ FSW(rn)));
            }
            #pragma unroll
            for (int mt = 0; mt < 2; mt++)
                #pragma unroll
                for (int p = 0; p < 4; p++) {
                    hmma16816(acc[mt][2 * p],     afr[mt], bfr[p][0], bfr[p][1]);
                    hmma16816(acc[mt][2 * p + 1], afr[mt], bfr[p][2], bfr[p][3]);
                }
        }

        if ((g & 7) == 7) {
            const int ctaM = (bid + (g >> 3) * grid) * 192;
            #pragma unroll
            for (int mt = 0; mt < 2; mt++) {
                const int r0 = ctaM + wm * 32 + mt * 16 + (lane >> 2);
                const int r1 = r0 + 8;
                #pragma unroll
                for (int nf = 0; nf < 8; nf++) {
                    const int col = wn * 64 + nf * 8 + (lane & 3) * 2;
                    if (r0 < n_nodes)
                        *(uint32_t*)&g_P[(size_t)r0 * 128 + col] = pack_h2(acc[mt][nf][0], acc[mt][nf][1]);
                    if (r1 < n_nodes)
                        *(uint32_t*)&g_P[(size_t)r1 * 128 + col] = pack_h2(acc[mt][nf][2], acc[mt][nf][3]);
                    acc[mt][nf][0] = acc[mt][nf][1] = acc[mt][nf][2] = acc[mt][nf][3] = 0.0f;
                }
            }
        }

        __syncthreads();  // consume(g) done by all warps; STSA(g+1) visible -> next iter invariant
    }
}

// ---------------- kernel 2: per-triple gather-combine, 2 triples/thread, fp16 P ----------------
__global__ __launch_bounds__(256) void gather_kernel(const int* __restrict__ triples,
                                                     const float* __restrict__ b,
                                                     float* __restrict__ out, int n) {
    int t = blockIdx.x * blockDim.x + threadIdx.x;
    int half = (n + 1) >> 1;
    if (t >= half) return;
    int t2 = t + half;
    bool has2 = t2 < n;

    int s1 = triples[t],  r1 = triples[n + t],  o1 = triples[2 * n + t];
    int s2 = 0, r2 = 0, o2 = 0;
    if (has2) { s2 = triples[t2]; r2 = triples[n + t2]; o2 = triples[2 * n + t2]; }

    __half a1 = __ldg(&g_P[(size_t)s1 * 128 + r1]);
    __half c1 = __ldg(&g_P[(size_t)o1 * 128 + 64 + r1]);
    __half a2 = __float2half(0.f), c2 = __float2half(0.f);
    if (has2) {
        a2 = __ldg(&g_P[(size_t)s2 * 128 + r2]);
        c2 = __ldg(&g_P[(size_t)o2 * 128 + 64 + r2]);
    }

    out[t] = __half2float(a1) + __half2float(c1) + __ldg(&b[r1]);
    if (has2) out[t2] = __half2float(a2) + __half2float(c2) + __ldg(&b[r2]);
}

extern "C" void kernel_launch(void* const* d_in, const int* in_sizes, int n_in,
                              void* d_out, int out_size)
{
    const float* emb     = (const float*)d_in[0];
    const float* W       = (const float*)d_in[1];
    const float* b       = (const float*)d_in[2];
    const int*   triples = (const int*)d_in[3];
    float*       out     = (float*)d_out;

    int n_nodes = in_sizes[0] / N_DIM;    // 100000
    int n_tr    = in_sizes[3] / 3;        // 200000
    int ntiles  = (n_nodes + 191) / 192;  // 521

    static int nsm = 0;
    if (nsm == 0) {
        cudaDeviceGetAttribute(&nsm, cudaDevAttrMultiProcessorCount, 0);
        cudaFuncSetAttribute(gemm_kernel, cudaFuncAttributeMaxDynamicSharedMemorySize, SMEM_BYTES);
    }
    int grid = (ntiles < nsm) ? ntiles : nsm;

    gemm_kernel<<<grid, 384, SMEM_BYTES>>>(emb, W, n_nodes, ntiles, grid);
    gather_kernel<<<((n_tr + 1) / 2 + 255) / 256, 256>>>(triples, b, out, n_tr);
}